// round 6
// baseline (speedup 1.0000x reference)
#include <cuda_runtime.h>
#include <cstdint>
#include <cstddef>

// Problem constants (fixed shapes per reference: B=4, T=4096, D=2048, G=16)
#define M_TOK 16384
#define DDIM  2048
#define BM 128
#define BN 128
#define BK 32
#define STAGES 3
#define PAD 36          // smem row stride in floats (32 data + 4 pad) -> conflict-free

// Scratch for q,k,v: 3 * 16384 * 2048 floats = 402 MB (device-global, no alloc)
__device__ float g_qkv[(size_t)3 * M_TOK * DDIM];

__device__ __forceinline__ uint32_t cvt_tf32(float x) {
    uint32_t r;
    asm("cvt.rna.tf32.f32 %0, %1;" : "=r"(r) : "f"(x));
    return r;
}

__device__ __forceinline__ void mma_tf32(float* d, const uint32_t* a, const uint32_t* b) {
    asm volatile(
        "mma.sync.aligned.m16n8k8.row.col.f32.tf32.tf32.f32 "
        "{%0,%1,%2,%3}, {%4,%5,%6,%7}, {%8,%9}, {%0,%1,%2,%3};\n"
        : "+f"(d[0]), "+f"(d[1]), "+f"(d[2]), "+f"(d[3])
        : "r"(a[0]), "r"(a[1]), "r"(a[2]), "r"(a[3]), "r"(b[0]), "r"(b[1]));
}

__device__ __forceinline__ void cp16(uint32_t saddr, const float* g) {
    asm volatile("cp.async.cg.shared.global [%0], [%1], 16;\n" :: "r"(saddr), "l"(g));
}

extern __shared__ float smem_dyn[];

// ---------------------------------------------------------------------------
// Kernel 1: fused QKV GEMM. q|k|v[m,n] = sum_k x[m,k]*W[n,k] + b[n]
// grid = (48 n-tiles [16 per matrix], 128 m-tiles), block = 256 threads
// ---------------------------------------------------------------------------
__global__ void __launch_bounds__(256, 2) qkv_gemm(
    const float* __restrict__ x,
    const float* __restrict__ Wq, const float* __restrict__ bq,
    const float* __restrict__ Wk, const float* __restrict__ bk,
    const float* __restrict__ Wv, const float* __restrict__ bv)
{
    const int tid  = threadIdx.x;
    const int lane = tid & 31;
    const int warp = tid >> 5;
    const int wm   = warp & 1;    // 2 warps along M
    const int wn   = warp >> 1;   // 4 warps along N

    const int ntile = blockIdx.x;         // 0..47
    const int mtile = blockIdx.y;         // 0..127
    const int wsel  = ntile >> 4;         // 0=q 1=k 2=v
    const int n0    = (ntile & 15) * BN;
    const int m0    = mtile * BM;

    const float* W    = (wsel == 0) ? Wq : (wsel == 1) ? Wk : Wv;
    const float* bias = (wsel == 0) ? bq : (wsel == 1) ? bk : bv;

    const int SASZ = BM * PAD;            // floats per stage (A == B size)
    float* sA = smem_dyn;                 // [STAGES][BM][PAD]
    float* sB = smem_dyn + STAGES * SASZ; // [STAGES][BN][PAD]

    const uint32_t sa_base = (uint32_t)__cvta_generic_to_shared(sA);
    const uint32_t sb_base = (uint32_t)__cvta_generic_to_shared(sB);

    // One 128x32 fp32 tile = 1024 x 16B chunks; 256 threads -> 4 chunks each.
    const int c_r[4]   = { (tid + 0*256) >> 3, (tid + 1*256) >> 3,
                           (tid + 2*256) >> 3, (tid + 3*256) >> 3 };
    const int c_col    = (tid & 7) * 4;

    auto issue_tile = [&](int kb, int st) {
        const int k0 = kb * BK;
        const uint32_t sa = sa_base + (uint32_t)(st * SASZ) * 4u;
        const uint32_t sb = sb_base + (uint32_t)(st * SASZ) * 4u;
        #pragma unroll
        for (int i = 0; i < 4; i++) {
            const int r = c_r[i];
            cp16(sa + (uint32_t)(r * PAD + c_col) * 4u,
                 x + (size_t)(m0 + r) * DDIM + k0 + c_col);
            cp16(sb + (uint32_t)(r * PAD + c_col) * 4u,
                 W + (size_t)(n0 + r) * DDIM + k0 + c_col);
        }
    };

    const int KT = DDIM / BK;   // 64

    #pragma unroll
    for (int s = 0; s < STAGES - 1; s++) {
        issue_tile(s, s);
        asm volatile("cp.async.commit_group;\n");
    }

    float d[4][4][4];
    #pragma unroll
    for (int i = 0; i < 4; i++)
        #pragma unroll
        for (int j = 0; j < 4; j++)
            #pragma unroll
            for (int q = 0; q < 4; q++) d[i][j][q] = 0.0f;

    for (int kb = 0; kb < KT; kb++) {
        asm volatile("cp.async.wait_group 1;\n");
        __syncthreads();

        // prefetch STAGES-1 ahead (buffer was freed at last iteration's sync)
        const int nk = kb + STAGES - 1;
        if (nk < KT) issue_tile(nk, nk % STAGES);
        asm volatile("cp.async.commit_group;\n");

        const int st = kb % STAGES;
        const float* A  = sA + st * SASZ;
        const float* Bm = sB + st * SASZ;

        #pragma unroll
        for (int ks = 0; ks < 4; ks++) {
            const int kk = ks * 8;
            uint32_t a[4][4], b[4][2];
            #pragma unroll
            for (int mt = 0; mt < 4; mt++) {
                const int r  = wm * 64 + mt * 16 + (lane >> 2);
                const int cc = kk + (lane & 3);
                a[mt][0] = cvt_tf32(A[r * PAD + cc]);
                a[mt][1] = cvt_tf32(A[(r + 8) * PAD + cc]);
                a[mt][2] = cvt_tf32(A[r * PAD + cc + 4]);
                a[mt][3] = cvt_tf32(A[(r + 8) * PAD + cc + 4]);
            }
            #pragma unroll
            for (int nt = 0; nt < 4; nt++) {
                const int r  = wn * 32 + nt * 8 + (lane >> 2);
                const int cc = kk + (lane & 3);
                b[nt][0] = cvt_tf32(Bm[r * PAD + cc]);
                b[nt][1] = cvt_tf32(Bm[r * PAD + cc + 4]);
            }
            #pragma unroll
            for (int mt = 0; mt < 4; mt++)
                #pragma unroll
                for (int nt = 0; nt < 4; nt++)
                    mma_tf32(d[mt][nt], a[mt], b[nt]);
        }
    }

    // Epilogue: add bias, store to scratch
    float* out = g_qkv + (size_t)wsel * M_TOK * DDIM;
    #pragma unroll
    for (int mt = 0; mt < 4; mt++) {
        const int r0 = m0 + wm * 64 + mt * 16 + (lane >> 2);
        #pragma unroll
        for (int nt = 0; nt < 4; nt++) {
            const int c0 = n0 + wn * 32 + nt * 8 + (lane & 3) * 2;
            const float b0v = bias[c0], b1v = bias[c0 + 1];
            float2 v0 = make_float2(d[mt][nt][0] + b0v, d[mt][nt][1] + b1v);
            float2 v1 = make_float2(d[mt][nt][2] + b0v, d[mt][nt][3] + b1v);
            *(float2*)(out + (size_t)r0 * DDIM + c0)       = v0;
            *(float2*)(out + (size_t)(r0 + 8) * DDIM + c0) = v1;
        }
    }
}

// ---------------------------------------------------------------------------
// Kernel 2: per-token group attention. One block per token.
// scores[g,h] = q_g . k_h / sqrt(128); att = softmax_h; out[g,:] = att @ V
// ---------------------------------------------------------------------------
__global__ void __launch_bounds__(256) attn_kernel(float* __restrict__ out)
{
    const int m = blockIdx.x;
    const int t = threadIdx.x;

    __shared__ __align__(16) float sq[16 * 132];
    __shared__ __align__(16) float sk[16 * 132];
    __shared__ __align__(16) float sv[16 * 132];
    __shared__ float satt[256];

    const float* qr = g_qkv + (size_t)m * DDIM;
    const float* kr = g_qkv + (size_t)M_TOK * DDIM + (size_t)m * DDIM;
    const float* vr = g_qkv + (size_t)2 * M_TOK * DDIM + (size_t)m * DDIM;

    #pragma unroll
    for (int i = 0; i < 2; i++) {
        const int idx = t + i * 256;          // float4 index, 0..511
        const int row = idx >> 5;             // 32 float4 per 128-float row
        const int c4  = idx & 31;
        float4 a = ((const float4*)qr)[idx];
        float4 b = ((const float4*)kr)[idx];
        float4 c = ((const float4*)vr)[idx];
        *(float4*)(sq + row * 132 + c4 * 4) = a;
        *(float4*)(sk + row * 132 + c4 * 4) = b;
        *(float4*)(sv + row * 132 + c4 * 4) = c;
    }
    __syncthreads();

    // scores + softmax: thread t owns (g = t>>4, h = t&15)
    {
        const int g = t >> 4, h = t & 15;
        const float4* qv = (const float4*)(sq + g * 132);
        const float4* kv = (const float4*)(sk + h * 132);
        float s = 0.0f;
        #pragma unroll
        for (int i = 0; i < 32; i++) {
            float4 a = qv[i], b = kv[i];
            s += a.x * b.x + a.y * b.y + a.z * b.z + a.w * b.w;
        }
        s *= 0.08838834764831845f;  // 1/sqrt(128)

        float mx = s;
        #pragma unroll
        for (int j = 8; j; j >>= 1)
            mx = fmaxf(mx, __shfl_xor_sync(0xffffffffu, mx, j));
        const float e = __expf(s - mx);
        float sum = e;
        #pragma unroll
        for (int j = 8; j; j >>= 1)
            sum += __shfl_xor_sync(0xffffffffu, sum, j);
        satt[t] = e / sum;
    }
    __syncthreads();

    // out[g,d] = sum_h att[g,h] * v[h,d]; 8 outputs per thread, coalesced
    float* o = out + (size_t)m * DDIM;
    #pragma unroll
    for (int j = 0; j < 8; j++) {
        const int n  = t + j * 256;
        const int gg = n >> 7, dd = n & 127;
        const float* arow = satt + gg * 16;
        float acc = 0.0f;
        #pragma unroll
        for (int h = 0; h < 16; h++)
            acc += arow[h] * sv[h * 132 + dd];
        o[n] = acc;
    }
}

// ---------------------------------------------------------------------------
extern "C" void kernel_launch(void* const* d_in, const int* in_sizes, int n_in,
                              void* d_out, int out_size)
{
    const float* x  = (const float*)d_in[0];
    const float* Wq = (const float*)d_in[1];
    const float* bq = (const float*)d_in[2];
    const float* Wk = (const float*)d_in[3];
    const float* bk = (const float*)d_in[4];
    const float* Wv = (const float*)d_in[5];
    const float* bv = (const float*)d_in[6];
    float* out = (float*)d_out;

    const size_t smem_sz = (size_t)STAGES * 2 * BM * PAD * sizeof(float); // 110592 B
    cudaFuncSetAttribute(qkv_gemm, cudaFuncAttributeMaxDynamicSharedMemorySize,
                         (int)smem_sz);

    dim3 grid(48, 128);  // x = n-tile (W reuse across y), y = m-tile
    qkv_gemm<<<grid, 256, smem_sz>>>(x, Wq, bq, Wk, bk, Wv, bv);
    attn_kernel<<<M_TOK, 256>>>(out);
}

// round 15
// speedup vs baseline: 1.1114x; 1.1114x over previous
#include <cuda_runtime.h>
#include <cstdint>
#include <cstddef>

// Fixed shapes: B=4, T=4096, D=2048, G=16
#define M_TOK 16384
#define DDIM  2048
#define BM 256
#define BN 128
#define BK 32
#define STAGES 4
#define KT (DDIM / BK)          // 64
#define PAD 36                  // smem row stride in floats (144B) -> conflict-free

#define A_STG_F (BM * PAD)      // 9216 floats / stage
#define B_STG_F (BN * PAD)      // 4608 floats / stage
#define STG_F   (A_STG_F + B_STG_F)
#define SMEM_REQ (STAGES * STG_F * 4)   // 221184 B

// Scratch: qkv (402MB) + tf32-rounded x (134MB) + tf32-rounded W (50MB)
__device__ float g_qkv[(size_t)3 * M_TOK * DDIM];
__device__ float g_xc[(size_t)M_TOK * DDIM];
__device__ float g_wc[(size_t)3 * DDIM * DDIM];

__device__ __forceinline__ void cp16(uint32_t saddr, const float* g) {
    asm volatile("cp.async.cg.shared.global [%0], [%1], 16;\n" :: "r"(saddr), "l"(g));
}

__device__ __forceinline__ void mma_tf32(float* d, const uint32_t* a, const uint32_t* b) {
    asm volatile(
        "mma.sync.aligned.m16n8k8.row.col.f32.tf32.tf32.f32 "
        "{%0,%1,%2,%3}, {%4,%5,%6,%7}, {%8,%9}, {%0,%1,%2,%3};\n"
        : "+f"(d[0]), "+f"(d[1]), "+f"(d[2]), "+f"(d[3])
        : "r"(a[0]), "r"(a[1]), "r"(a[2]), "r"(a[3]), "r"(b[0]), "r"(b[1]));
}

__device__ __forceinline__ void ldsm4(uint32_t* r, uint32_t addr) {
    asm volatile("ldmatrix.sync.aligned.m8n8.x4.shared.b16 {%0,%1,%2,%3}, [%4];"
                 : "=r"(r[0]), "=r"(r[1]), "=r"(r[2]), "=r"(r[3]) : "r"(addr));
}

extern __shared__ float smem_dyn[];

// ---------------------------------------------------------------------------
// Kernel 0: round fp32 -> tf32 (rna) once, so the GEMM hot loop needs no CVT.
// ---------------------------------------------------------------------------
__global__ void __launch_bounds__(512) rna_kernel(const float4* __restrict__ src,
                                                  float4* __restrict__ dst, int n4)
{
    const int i = blockIdx.x * 512 + threadIdx.x;
    if (i >= n4) return;
    float4 v = src[i];
    uint32_t a, b, c, d;
    asm("cvt.rna.tf32.f32 %0, %1;" : "=r"(a) : "f"(v.x));
    asm("cvt.rna.tf32.f32 %0, %1;" : "=r"(b) : "f"(v.y));
    asm("cvt.rna.tf32.f32 %0, %1;" : "=r"(c) : "f"(v.z));
    asm("cvt.rna.tf32.f32 %0, %1;" : "=r"(d) : "f"(v.w));
    float4 o;
    o.x = __uint_as_float(a); o.y = __uint_as_float(b);
    o.z = __uint_as_float(c); o.w = __uint_as_float(d);
    dst[i] = o;
}

// ---------------------------------------------------------------------------
// Kernel 1: fused QKV GEMM. out[m,n] = sum_k x[m,k]*W[n,k] + b[n]
// grid = (48 n-tiles [16 per matrix], 64 m-tiles), 512 threads.
// Warp tile 64x32: wm = warp&3 (4 x 64 rows), wn = warp>>2 (4 x 32 cols).
// ---------------------------------------------------------------------------
__global__ void __launch_bounds__(512, 1) qkv_gemm(
    const float* __restrict__ bq, const float* __restrict__ bk,
    const float* __restrict__ bv)
{
    const int tid  = threadIdx.x;
    const int lane = tid & 31;
    const int warp = tid >> 5;
    const int wm   = warp & 3;
    const int wn   = warp >> 2;

    const int ntile = blockIdx.x;          // 0..47
    const int mtile = blockIdx.y;          // 0..63
    const int wsel  = ntile >> 4;          // 0=q 1=k 2=v
    const int n0    = (ntile & 15) * BN;
    const int m0    = mtile * BM;

    const float* x    = g_xc;
    const float* W    = g_wc + (size_t)wsel * DDIM * DDIM;
    const float* bias = (wsel == 0) ? bq : (wsel == 1) ? bk : bv;

    float* sA = smem_dyn;                      // [STAGES][BM][PAD]
    float* sB = smem_dyn + STAGES * A_STG_F;   // [STAGES][BN][PAD]
    const uint32_t sa_u = (uint32_t)__cvta_generic_to_shared(sA);
    const uint32_t sb_u = (uint32_t)__cvta_generic_to_shared(sB);

    // loader: A = 2048 chunks (4/thread), B = 1024 chunks (2/thread)
    auto issue_tile = [&](int kb, int st) {
        const int k0 = kb * BK;
        const uint32_t sa = sa_u + (uint32_t)(st * A_STG_F) * 4u;
        const uint32_t sb = sb_u + (uint32_t)(st * B_STG_F) * 4u;
        #pragma unroll
        for (int i = 0; i < 4; i++) {
            const int idx = tid + i * 512;
            const int r = idx >> 3, c = (idx & 7) * 4;
            cp16(sa + (uint32_t)(r * PAD + c) * 4u,
                 x + (size_t)(m0 + r) * DDIM + k0 + c);
        }
        #pragma unroll
        for (int i = 0; i < 2; i++) {
            const int idx = tid + i * 512;
            const int r = idx >> 3, c = (idx & 7) * 4;
            cp16(sb + (uint32_t)(r * PAD + c) * 4u,
                 W + (size_t)(n0 + r) * DDIM + k0 + c);
        }
    };

    #pragma unroll
    for (int s = 0; s < STAGES - 1; s++) {
        issue_tile(s, s);
        asm volatile("cp.async.commit_group;\n");
    }

    float d[4][4][4];
    #pragma unroll
    for (int i = 0; i < 4; i++)
        #pragma unroll
        for (int j = 0; j < 4; j++)
            #pragma unroll
            for (int q = 0; q < 4; q++) d[i][j][q] = 0.0f;

    // ldmatrix per-thread base offsets (in floats), independent of stage/ks
    const int oct  = lane >> 3;
    const int lrow = lane & 7;
    // A: octet0 rows+0 k+0 -> a0 | oct1 rows+8 k+0 -> a1 | oct2 rows+0 k+4 -> a2 | oct3 rows+8 k+4 -> a3
    const int a_off = (wm * 64 + (oct & 1) * 8 + lrow) * PAD + (oct >> 1) * 4;
    // B x4 covers nt pair: oct0 nt=2p k0 -> b[2p][0] | oct1 nt=2p k4 -> b[2p][1] | oct2/3 nt=2p+1
    const int b_off = (wn * 32 + (oct >> 1) * 8 + lrow) * PAD + (oct & 1) * 4;

    #pragma unroll 1
    for (int kb = 0; kb < KT; kb++) {
        asm volatile("cp.async.wait_group %0;\n" :: "n"(STAGES - 2));
        __syncthreads();

        const int st = kb % STAGES;
        const uint32_t a_base = sa_u + (uint32_t)(st * A_STG_F + a_off) * 4u;
        const uint32_t b_base = sb_u + (uint32_t)(st * B_STG_F + b_off) * 4u;

        #pragma unroll
        for (int ks = 0; ks < 4; ks++) {
            uint32_t a[4][4], b[2][4];
            #pragma unroll
            for (int mt = 0; mt < 4; mt++)
                ldsm4(a[mt], a_base + (uint32_t)(mt * 16 * PAD * 4 + ks * 32));
            #pragma unroll
            for (int p = 0; p < 2; p++)
                ldsm4(b[p], b_base + (uint32_t)(p * 16 * PAD * 4 + ks * 32));
            #pragma unroll
            for (int mt = 0; mt < 4; mt++)
                #pragma unroll
                for (int nt = 0; nt < 4; nt++)
                    mma_tf32(d[mt][nt], a[mt], &b[nt >> 1][(nt & 1) * 2]);
        }
        __syncthreads();

        const int nk = kb + STAGES - 1;
        if (nk < KT) issue_tile(nk, nk % STAGES);
        asm volatile("cp.async.commit_group;\n");
    }

    // Epilogue: bias + store to scratch
    float* out = g_qkv + (size_t)wsel * M_TOK * DDIM;
    #pragma unroll
    for (int mt = 0; mt < 4; mt++) {
        const int r0 = m0 + wm * 64 + mt * 16 + (lane >> 2);
        #pragma unroll
        for (int nt = 0; nt < 4; nt++) {
            const int c0 = n0 + wn * 32 + nt * 8 + (lane & 3) * 2;
            const float b0v = bias[c0], b1v = bias[c0 + 1];
            float2 v0 = make_float2(d[mt][nt][0] + b0v, d[mt][nt][1] + b1v);
            float2 v1 = make_float2(d[mt][nt][2] + b0v, d[mt][nt][3] + b1v);
            *(float2*)(out + (size_t)r0 * DDIM + c0)       = v0;
            *(float2*)(out + (size_t)(r0 + 8) * DDIM + c0) = v1;
        }
    }
}

// ---------------------------------------------------------------------------
// Kernel 2: per-token group attention. One block per token.
// ---------------------------------------------------------------------------
__global__ void __launch_bounds__(256) attn_kernel(float* __restrict__ out)
{
    const int m = blockIdx.x;
    const int t = threadIdx.x;

    __shared__ __align__(16) float sq[16 * 132];
    __shared__ __align__(16) float sk[16 * 132];
    __shared__ __align__(16) float sv[16 * 132];
    __shared__ float satt[256];

    const float* qr = g_qkv + (size_t)m * DDIM;
    const float* kr = g_qkv + (size_t)M_TOK * DDIM + (size_t)m * DDIM;
    const float* vr = g_qkv + (size_t)2 * M_TOK * DDIM + (size_t)m * DDIM;

    #pragma unroll
    for (int i = 0; i < 2; i++) {
        const int idx = t + i * 256;          // float4 index, 0..511
        const int row = idx >> 5;
        const int c4  = idx & 31;
        float4 a = ((const float4*)qr)[idx];
        float4 b = ((const float4*)kr)[idx];
        float4 c = ((const float4*)vr)[idx];
        *(float4*)(sq + row * 132 + c4 * 4) = a;
        *(float4*)(sk + row * 132 + c4 * 4) = b;
        *(float4*)(sv + row * 132 + c4 * 4) = c;
    }
    __syncthreads();

    {
        const int g = t >> 4, h = t & 15;
        const float4* qv = (const float4*)(sq + g * 132);
        const float4* kv = (const float4*)(sk + h * 132);
        float s = 0.0f;
        #pragma unroll
        for (int i = 0; i < 32; i++) {
            float4 a = qv[i], b = kv[i];
            s += a.x * b.x + a.y * b.y + a.z * b.z + a.w * b.w;
        }
        s *= 0.08838834764831845f;  // 1/sqrt(128)

        float mx = s;
        #pragma unroll
        for (int j = 8; j; j >>= 1)
            mx = fmaxf(mx, __shfl_xor_sync(0xffffffffu, mx, j));
        const float e = __expf(s - mx);
        float sum = e;
        #pragma unroll
        for (int j = 8; j; j >>= 1)
            sum += __shfl_xor_sync(0xffffffffu, sum, j);
        satt[t] = e / sum;
    }
    __syncthreads();

    // out[g,d] = sum_h att[g,h] * v[h,d]; float4 per thread
    float* o = out + (size_t)m * DDIM;
    #pragma unroll
    for (int j = 0; j < 2; j++) {
        const int n  = t + j * 256;           // float4 index 0..511
        const int gg = n >> 5;
        const int d4 = n & 31;
        const float* arow = satt + gg * 16;
        float4 acc = make_float4(0.f, 0.f, 0.f, 0.f);
        #pragma unroll
        for (int h = 0; h < 16; h++) {
            const float a = arow[h];
            float4 v4 = *(const float4*)(sv + h * 132 + d4 * 4);
            acc.x += a * v4.x; acc.y += a * v4.y;
            acc.z += a * v4.z; acc.w += a * v4.w;
        }
        *(float4*)(o + gg * 128 + d4 * 4) = acc;
    }
}

// ---------------------------------------------------------------------------
extern "C" void kernel_launch(void* const* d_in, const int* in_sizes, int n_in,
                              void* d_out, int out_size)
{
    const float* x  = (const float*)d_in[0];
    const float* Wq = (const float*)d_in[1];
    const float* bq = (const float*)d_in[2];
    const float* Wk = (const float*)d_in[3];
    const float* bk = (const float*)d_in[4];
    const float* Wv = (const float*)d_in[5];
    const float* bv = (const float*)d_in[6];
    float* out = (float*)d_out;

    float* xc; float* wc; float* dummy;
    cudaGetSymbolAddress((void**)&xc, g_xc);
    cudaGetSymbolAddress((void**)&wc, g_wc);
    cudaGetSymbolAddress((void**)&dummy, g_qkv);

    // Pre-round inputs to tf32 (rna) so the GEMM needs no CVT in the hot loop.
    const int nx4 = (M_TOK * DDIM) / 4;          // 8388608
    const int nw4 = (DDIM * DDIM) / 4;           // 1048576
    rna_kernel<<<(nx4 + 511) / 512, 512>>>((const float4*)x,  (float4*)xc, nx4);
    rna_kernel<<<(nw4 + 511) / 512, 512>>>((const float4*)Wq, (float4*)(wc + (size_t)0 * DDIM * DDIM), nw4);
    rna_kernel<<<(nw4 + 511) / 512, 512>>>((const float4*)Wk, (float4*)(wc + (size_t)1 * DDIM * DDIM), nw4);
    rna_kernel<<<(nw4 + 511) / 512, 512>>>((const float4*)Wv, (float4*)(wc + (size_t)2 * DDIM * DDIM), nw4);

    cudaFuncSetAttribute(qkv_gemm, cudaFuncAttributeMaxDynamicSharedMemorySize,
                         SMEM_REQ);
    dim3 grid(48, 64);  // x = n-tile (16 per matrix x 3), y = m-tile
    qkv_gemm<<<grid, 512, SMEM_REQ>>>(bq, bk, bv);
    attn_kernel<<<M_TOK, 256>>>(out);
}

// round 16
// speedup vs baseline: 2.1218x; 1.9091x over previous
#include <cuda_runtime.h>
#include <cuda_fp16.h>
#include <cstdint>
#include <cstddef>

// Fixed shapes: B=4, T=4096, D=2048, G=16
#define M_TOK 16384
#define DDIM  2048
#define BM 256
#define BN 128
#define BK 64                   // 64 fp16 = 128B per row per stage
#define STAGES 4
#define KT (DDIM / BK)          // 32
#define ROWB 144                // smem row stride bytes (128 data + 16 pad)

#define A_STG_B (BM * ROWB)     // 36864 B
#define B_STG_B (BN * ROWB)     // 18432 B
#define STG_B   (A_STG_B + B_STG_B)        // 55296 B
#define SMEM_REQ (STAGES * STG_B)          // 221184 B

// Scratch: qkv fp32 (402MB) + fp16 x (67MB) + fp16 W (50MB)
__device__ float  g_qkv[(size_t)3 * M_TOK * DDIM];
__device__ __half g_xh[(size_t)M_TOK * DDIM];
__device__ __half g_wh[(size_t)3 * DDIM * DDIM];

__device__ __forceinline__ void cp16(uint32_t saddr, const void* g) {
    asm volatile("cp.async.cg.shared.global [%0], [%1], 16;\n" :: "r"(saddr), "l"(g));
}

__device__ __forceinline__ void mma_f16(float* d, const uint32_t* a, const uint32_t* b) {
    asm volatile(
        "mma.sync.aligned.m16n8k16.row.col.f32.f16.f16.f32 "
        "{%0,%1,%2,%3}, {%4,%5,%6,%7}, {%8,%9}, {%0,%1,%2,%3};\n"
        : "+f"(d[0]), "+f"(d[1]), "+f"(d[2]), "+f"(d[3])
        : "r"(a[0]), "r"(a[1]), "r"(a[2]), "r"(a[3]), "r"(b[0]), "r"(b[1]));
}

__device__ __forceinline__ void ldsm4(uint32_t* r, uint32_t addr) {
    asm volatile("ldmatrix.sync.aligned.m8n8.x4.shared.b16 {%0,%1,%2,%3}, [%4];"
                 : "=r"(r[0]), "=r"(r[1]), "=r"(r[2]), "=r"(r[3]) : "r"(addr));
}

extern __shared__ char smem_dyn[];

// ---------------------------------------------------------------------------
// Kernel 0: fp32 -> fp16 conversion (one pass; GEMM hot loop needs no CVT)
// ---------------------------------------------------------------------------
__global__ void __launch_bounds__(512) cvt_half(const float4* __restrict__ src,
                                                uint2* __restrict__ dst, int n4)
{
    const int i = blockIdx.x * 512 + threadIdx.x;
    if (i >= n4) return;
    float4 v = src[i];
    __half2 lo = __floats2half2_rn(v.x, v.y);
    __half2 hi = __floats2half2_rn(v.z, v.w);
    uint2 o;
    o.x = *reinterpret_cast<uint32_t*>(&lo);
    o.y = *reinterpret_cast<uint32_t*>(&hi);
    dst[i] = o;
}

// ---------------------------------------------------------------------------
// Kernel 1: fused QKV GEMM (fp16 in, fp32 accum). out[m,n] = x[m,:].W[n,:] + b[n]
// grid = (48 n-tiles [16 per matrix], 64 m-tiles), 512 threads.
// Warp tile 64x32: wm = warp&3, wn = warp>>2.
// ---------------------------------------------------------------------------
__global__ void __launch_bounds__(512, 1) qkv_gemm(
    const float* __restrict__ bq, const float* __restrict__ bk,
    const float* __restrict__ bv)
{
    const int tid  = threadIdx.x;
    const int lane = tid & 31;
    const int warp = tid >> 5;
    const int wm   = warp & 3;
    const int wn   = warp >> 2;

    const int ntile = blockIdx.x;          // 0..47
    const int mtile = blockIdx.y;          // 0..63
    const int wsel  = ntile >> 4;          // 0=q 1=k 2=v
    const int n0    = (ntile & 15) * BN;
    const int m0    = mtile * BM;

    const __half* x    = g_xh;
    const __half* W    = g_wh + (size_t)wsel * DDIM * DDIM;
    const float*  bias = (wsel == 0) ? bq : (wsel == 1) ? bk : bv;

    const uint32_t sbase = (uint32_t)__cvta_generic_to_shared(smem_dyn);

    // loader: A = 2048 16B-chunks (4/thread), B = 1024 (2/thread)
    auto issue_tile = [&](int kb, int st) {
        const int k0 = kb * BK;
        const uint32_t sa = sbase + (uint32_t)(st * STG_B);
        const uint32_t sb = sa + A_STG_B;
        #pragma unroll
        for (int i = 0; i < 4; i++) {
            const int idx = tid + i * 512;
            const int r = idx >> 3, c = (idx & 7);          // chunk c: 8 fp16 = 16B
            cp16(sa + (uint32_t)(r * ROWB + c * 16),
                 x + (size_t)(m0 + r) * DDIM + k0 + c * 8);
        }
        #pragma unroll
        for (int i = 0; i < 2; i++) {
            const int idx = tid + i * 512;
            const int r = idx >> 3, c = (idx & 7);
            cp16(sb + (uint32_t)(r * ROWB + c * 16),
                 W + (size_t)(n0 + r) * DDIM + k0 + c * 8);
        }
    };

    #pragma unroll
    for (int s = 0; s < STAGES - 1; s++) {
        issue_tile(s, s);
        asm volatile("cp.async.commit_group;\n");
    }

    float d[4][4][4];
    #pragma unroll
    for (int i = 0; i < 4; i++)
        #pragma unroll
        for (int j = 0; j < 4; j++)
            #pragma unroll
            for (int q = 0; q < 4; q++) d[i][j][q] = 0.0f;

    // ldmatrix per-thread base byte offsets (stage/mt/ks independent)
    const int oct  = lane >> 3;
    const int lrow = lane & 7;
    // A m16k16 quadrants: oct0 rows+0,k+0 | oct1 rows+8,k+0 | oct2 rows+0,k+16B | oct3 rows+8,k+16B
    const int a_off = (wm * 64 + (oct & 1) * 8 + lrow) * ROWB + (oct >> 1) * 16;
    // B n16k16: oct0 n+0,k+0 | oct1 n+0,k+16B | oct2 n+8,k+0 | oct3 n+8,k+16B
    const int b_off = (wn * 32 + (oct >> 1) * 8 + lrow) * ROWB + (oct & 1) * 16;

    #pragma unroll 1
    for (int kb = 0; kb < KT; kb++) {
        asm volatile("cp.async.wait_group %0;\n" :: "n"(STAGES - 2));
        __syncthreads();   // stage kb ready; stage kb-1 fully consumed by all warps

        const int nk = kb + STAGES - 1;
        if (nk < KT) issue_tile(nk, nk % STAGES);
        asm volatile("cp.async.commit_group;\n");

        const int st = kb % STAGES;
        const uint32_t a_base = sbase + (uint32_t)(st * STG_B) + (uint32_t)a_off;
        const uint32_t b_base = sbase + (uint32_t)(st * STG_B + A_STG_B) + (uint32_t)b_off;

        #pragma unroll
        for (int ks = 0; ks < 4; ks++) {            // 4 x k16
            uint32_t a[4][4], b[2][4];
            #pragma unroll
            for (int mt = 0; mt < 4; mt++)
                ldsm4(a[mt], a_base + (uint32_t)(mt * 16 * ROWB + ks * 32));
            #pragma unroll
            for (int p = 0; p < 2; p++)
                ldsm4(b[p], b_base + (uint32_t)(p * 16 * ROWB + ks * 32));
            #pragma unroll
            for (int mt = 0; mt < 4; mt++)
                #pragma unroll
                for (int nt = 0; nt < 4; nt++)
                    mma_f16(d[mt][nt], a[mt], &b[nt >> 1][(nt & 1) * 2]);
        }
    }

    // Epilogue: bias + store fp32 to scratch
    float* out = g_qkv + (size_t)wsel * M_TOK * DDIM;
    #pragma unroll
    for (int mt = 0; mt < 4; mt++) {
        const int r0 = m0 + wm * 64 + mt * 16 + (lane >> 2);
        #pragma unroll
        for (int nt = 0; nt < 4; nt++) {
            const int c0 = n0 + wn * 32 + nt * 8 + (lane & 3) * 2;
            const float b0v = bias[c0], b1v = bias[c0 + 1];
            float2 v0 = make_float2(d[mt][nt][0] + b0v, d[mt][nt][1] + b1v);
            float2 v1 = make_float2(d[mt][nt][2] + b0v, d[mt][nt][3] + b1v);
            *(float2*)(out + (size_t)r0 * DDIM + c0)       = v0;
            *(float2*)(out + (size_t)(r0 + 8) * DDIM + c0) = v1;
        }
    }
}

// ---------------------------------------------------------------------------
// Kernel 2: per-token group attention. One block per token.
// ---------------------------------------------------------------------------
__global__ void __launch_bounds__(256) attn_kernel(float* __restrict__ out)
{
    const int m = blockIdx.x;
    const int t = threadIdx.x;

    __shared__ __align__(16) float sq[16 * 132];
    __shared__ __align__(16) float sk[16 * 132];
    __shared__ __align__(16) float sv[16 * 132];
    __shared__ float satt[256];

    const float* qr = g_qkv + (size_t)m * DDIM;
    const float* kr = g_qkv + (size_t)M_TOK * DDIM + (size_t)m * DDIM;
    const float* vr = g_qkv + (size_t)2 * M_TOK * DDIM + (size_t)m * DDIM;

    #pragma unroll
    for (int i = 0; i < 2; i++) {
        const int idx = t + i * 256;          // float4 index, 0..511
        const int row = idx >> 5;
        const int c4  = idx & 31;
        float4 a = ((const float4*)qr)[idx];
        float4 b = ((const float4*)kr)[idx];
        float4 c = ((const float4*)vr)[idx];
        *(float4*)(sq + row * 132 + c4 * 4) = a;
        *(float4*)(sk + row * 132 + c4 * 4) = b;
        *(float4*)(sv + row * 132 + c4 * 4) = c;
    }
    __syncthreads();

    {
        const int g = t >> 4, h = t & 15;
        const float4* qv = (const float4*)(sq + g * 132);
        const float4* kv = (const float4*)(sk + h * 132);
        float s = 0.0f;
        #pragma unroll
        for (int i = 0; i < 32; i++) {
            float4 a = qv[i], b = kv[i];
            s += a.x * b.x + a.y * b.y + a.z * b.z + a.w * b.w;
        }
        s *= 0.08838834764831845f;  // 1/sqrt(128)

        float mx = s;
        #pragma unroll
        for (int j = 8; j; j >>= 1)
            mx = fmaxf(mx, __shfl_xor_sync(0xffffffffu, mx, j));
        const float e = __expf(s - mx);
        float sum = e;
        #pragma unroll
        for (int j = 8; j; j >>= 1)
            sum += __shfl_xor_sync(0xffffffffu, sum, j);
        satt[t] = e / sum;
    }
    __syncthreads();

    // out[g,d] = sum_h att[g,h] * v[h,d]; float4 per thread
    float* o = out + (size_t)m * DDIM;
    #pragma unroll
    for (int j = 0; j < 2; j++) {
        const int n  = t + j * 256;           // float4 index 0..511
        const int gg = n >> 5;
        const int d4 = n & 31;
        const float* arow = satt + gg * 16;
        float4 acc = make_float4(0.f, 0.f, 0.f, 0.f);
        #pragma unroll
        for (int h = 0; h < 16; h++) {
            const float a = arow[h];
            float4 v4 = *(const float4*)(sv + h * 132 + d4 * 4);
            acc.x += a * v4.x; acc.y += a * v4.y;
            acc.z += a * v4.z; acc.w += a * v4.w;
        }
        *(float4*)(o + gg * 128 + d4 * 4) = acc;
    }
}

// ---------------------------------------------------------------------------
extern "C" void kernel_launch(void* const* d_in, const int* in_sizes, int n_in,
                              void* d_out, int out_size)
{
    const float* x  = (const float*)d_in[0];
    const float* Wq = (const float*)d_in[1];
    const float* bq = (const float*)d_in[2];
    const float* Wk = (const float*)d_in[3];
    const float* bk = (const float*)d_in[4];
    const float* Wv = (const float*)d_in[5];
    const float* bv = (const float*)d_in[6];
    float* out = (float*)d_out;

    __half* xh; __half* wh;
    cudaGetSymbolAddress((void**)&xh, g_xh);
    cudaGetSymbolAddress((void**)&wh, g_wh);

    const int nx4 = (M_TOK * DDIM) / 4;          // 8388608
    const int nw4 = (DDIM * DDIM) / 4;           // 1048576
    cvt_half<<<(nx4 + 511) / 512, 512>>>((const float4*)x,  (uint2*)xh, nx4);
    cvt_half<<<(nw4 + 511) / 512, 512>>>((const float4*)Wq, (uint2*)(wh + (size_t)0 * DDIM * DDIM), nw4);
    cvt_half<<<(nw4 + 511) / 512, 512>>>((const float4*)Wk, (uint2*)(wh + (size_t)1 * DDIM * DDIM), nw4);
    cvt_half<<<(nw4 + 511) / 512, 512>>>((const float4*)Wv, (uint2*)(wh + (size_t)2 * DDIM * DDIM), nw4);

    cudaFuncSetAttribute(qkv_gemm, cudaFuncAttributeMaxDynamicSharedMemorySize,
                         SMEM_REQ);
    dim3 grid(48, 64);  // x = n-tile (16 per matrix x 3), y = m-tile
    qkv_gemm<<<grid, 512, SMEM_REQ>>>(bq, bk, bv);
    attn_kernel<<<M_TOK, 256>>>(out);
}